// round 4
// baseline (speedup 1.0000x reference)
#include <cuda_runtime.h>
#include <cuda_bf16.h>

// Problem shape (fixed): B=4, S=2048 -> N=8192 rows, D=4096, O=4096, k=1024.
#define N_MAX 8192
#define O_MAX 4096
#define CAP   32          // max boundary candidates per row (avg ~1.3)
#define BAND_EPS 1e-4f    // >> fp32 gemm error bound (~2e-5 max)

// Scratch (device globals are the sanctioned alternative to cudaMalloc):
__device__ float         g_router[(size_t)N_MAX * O_MAX];
__device__ unsigned char g_mask  [(size_t)N_MAX * O_MAX];
__device__ int           g_cand  [(size_t)N_MAX * CAP];
__device__ double        g_exact [(size_t)N_MAX * CAP];
__device__ int           g_need  [N_MAX];
__device__ int           g_ccnt  [N_MAX];

// ---------------------------------------------------------------------------
// fp32 SGEMM:  C[n,o] = dot(A[n,:], W[o,:]) + bias[o]
// mode 0: C = acc + bias          (router pass)
// mode 1: C = (acc + bias) * mask (orig pass)
// ---------------------------------------------------------------------------
#define BM 128
#define BN 128
#define BK 8
#define TM 8
#define TN 8

__global__ __launch_bounds__(256)
void gemm_nt_kernel(const float* __restrict__ A,
                    const float* __restrict__ W,
                    const float* __restrict__ bias,
                    float* __restrict__ C,
                    const unsigned char* __restrict__ mask,
                    int N, int O, int D, int mode)
{
    __shared__ float As[BK][BM];
    __shared__ float Bs[BK][BN];

    const int bm = blockIdx.y * BM;
    const int bn = blockIdx.x * BN;
    const int tid = threadIdx.x;
    const int tx = tid & 15;
    const int ty = tid >> 4;

    const int loadRow = tid >> 1;
    const int loadCol = (tid & 1) * 4;

    const bool aRowOk = (bm + loadRow) < N;
    const bool wRowOk = (bn + loadRow) < O;
    const float* Aptr = A + (size_t)(bm + loadRow) * D + loadCol;
    const float* Wptr = W + (size_t)(bn + loadRow) * D + loadCol;

    float acc[TM][TN];
#pragma unroll
    for (int i = 0; i < TM; i++)
#pragma unroll
        for (int j = 0; j < TN; j++) acc[i][j] = 0.0f;

    for (int k0 = 0; k0 < D; k0 += BK) {
        float4 av = aRowOk ? *(const float4*)(Aptr + k0) : make_float4(0.f, 0.f, 0.f, 0.f);
        float4 wv = wRowOk ? *(const float4*)(Wptr + k0) : make_float4(0.f, 0.f, 0.f, 0.f);
        As[loadCol + 0][loadRow] = av.x;
        As[loadCol + 1][loadRow] = av.y;
        As[loadCol + 2][loadRow] = av.z;
        As[loadCol + 3][loadRow] = av.w;
        Bs[loadCol + 0][loadRow] = wv.x;
        Bs[loadCol + 1][loadRow] = wv.y;
        Bs[loadCol + 2][loadRow] = wv.z;
        Bs[loadCol + 3][loadRow] = wv.w;
        __syncthreads();

#pragma unroll
        for (int kk = 0; kk < BK; kk++) {
            float a[TM], b[TN];
            float4 a0 = *(const float4*)&As[kk][ty * TM];
            float4 a1 = *(const float4*)&As[kk][ty * TM + 4];
            a[0] = a0.x; a[1] = a0.y; a[2] = a0.z; a[3] = a0.w;
            a[4] = a1.x; a[5] = a1.y; a[6] = a1.z; a[7] = a1.w;
            float4 b0 = *(const float4*)&Bs[kk][tx * TN];
            float4 b1 = *(const float4*)&Bs[kk][tx * TN + 4];
            b[0] = b0.x; b[1] = b0.y; b[2] = b0.z; b[3] = b0.w;
            b[4] = b1.x; b[5] = b1.y; b[6] = b1.z; b[7] = b1.w;
#pragma unroll
            for (int i = 0; i < TM; i++)
#pragma unroll
                for (int j = 0; j < TN; j++)
                    acc[i][j] = fmaf(a[i], b[j], acc[i][j]);
        }
        __syncthreads();
    }

#pragma unroll
    for (int i = 0; i < TM; i++) {
        const int row = bm + ty * TM + i;
        if (row >= N) continue;
#pragma unroll
        for (int j = 0; j < TN; j++) {
            const int col = bn + tx * TN + j;
            if (col >= O) continue;
            float v = acc[i][j] + bias[col];
            const size_t idx = (size_t)row * O + col;
            if (mode == 0) C[idx] = v;
            else           C[idx] = mask[idx] ? v : 0.0f;
        }
    }
}

// ---------------------------------------------------------------------------
// Per-row top-k selection with boundary-band candidate extraction.
// Radix-selects the exact fp32 k-th value T, writes definite in/out mask,
// and records elements within +-BAND_EPS of T for exact fp64 re-ranking.
// ---------------------------------------------------------------------------
#define TPK_THREADS 256

__device__ __forceinline__ unsigned int f2key(float f) {
    unsigned int b = __float_as_uint(f);
    return (b & 0x80000000u) ? ~b : (b | 0x80000000u);
}
__device__ __forceinline__ float key2f(unsigned int u) {
    unsigned int b = (u & 0x80000000u) ? (u ^ 0x80000000u) : ~u;
    return __uint_as_float(b);
}

__global__ __launch_bounds__(TPK_THREADS)
void topk_select_kernel(const float* __restrict__ R,
                        unsigned char* __restrict__ mask,
                        int O, int k)
{
    __shared__ float s[O_MAX];
    __shared__ unsigned int hist[256];
    __shared__ unsigned int s_prefix, s_prefMask, s_rem;
    __shared__ int s_G, s_C, s_fallback;

    const int row = blockIdx.x;
    const float* r = R + (size_t)row * O;
    unsigned char* mrow = mask + (size_t)row * O;

    for (int i = threadIdx.x; i < O; i += TPK_THREADS) s[i] = r[i];
    if (threadIdx.x == 0) {
        s_prefix = 0u; s_prefMask = 0u; s_rem = (unsigned int)k;
        s_G = 0; s_C = 0; s_fallback = 0;
    }
    __syncthreads();

    // 4-pass radix select (MSB->LSB) for the exact fp32 k-th largest value.
    for (int pass = 0; pass < 4; pass++) {
        const int shift = 24 - 8 * pass;
        hist[threadIdx.x] = 0u;
        __syncthreads();
        const unsigned int pm = s_prefMask;
        const unsigned int pv = s_prefix;
        for (int i = threadIdx.x; i < O; i += TPK_THREADS) {
            unsigned int u = f2key(s[i]);
            if ((u & pm) == pv)
                atomicAdd(&hist[(u >> shift) & 0xFFu], 1u);
        }
        __syncthreads();
        if (threadIdx.x == 0) {
            unsigned int cum = 0;
            int b = 255;
            for (; b >= 0; b--) {
                unsigned int c = hist[b];
                if (cum + c >= s_rem) { s_rem -= cum; break; }
                cum += c;
            }
            if (b < 0) b = 0;
            s_prefix |= ((unsigned int)b) << shift;
            s_prefMask |= 0xFFu << shift;
        }
        __syncthreads();
    }

    const unsigned int kT = s_prefix;
    const float T = key2f(kT);
    const float hi = T + BAND_EPS;
    const float lo = T - BAND_EPS;

    // Band classification: definite-in / candidate / definite-out.
    for (int i = threadIdx.x; i < O; i += TPK_THREADS) {
        float v = s[i];
        if (v > hi) {
            mrow[i] = 1;
            atomicAdd(&s_G, 1);
        } else {
            mrow[i] = 0;
            if (v >= lo) {
                int p = atomicAdd(&s_C, 1);
                if (p < CAP) g_cand[(size_t)row * CAP + p] = i;
            }
        }
    }
    __syncthreads();

    if (threadIdx.x == 0) {
        if (s_C <= CAP) {
            g_ccnt[row] = s_C;
            int need = k - s_G;
            if (need < 0) need = 0;
            if (need > s_C) need = s_C;
            g_need[row] = need;
        } else {
            s_fallback = 1;          // pathological tie explosion: fp32 rule
            g_ccnt[row] = 0;
            g_need[row] = 0;
        }
    }
    __syncthreads();

    if (s_fallback) {
        for (int i = threadIdx.x; i < O; i += TPK_THREADS)
            mrow[i] = (f2key(s[i]) > kT) ? 1 : 0;
        __syncthreads();
        if (threadIdx.x == 0) {
            int q = (int)s_rem;
            for (int i = 0; i < O && q > 0; i++)
                if (f2key(s[i]) == kT) { mrow[i] = 1; q--; }
        }
    }
}

// ---------------------------------------------------------------------------
// Exact fp64 router score for each boundary candidate.
// grid = (CAP, N); inactive blocks exit immediately.
// ---------------------------------------------------------------------------
__global__ __launch_bounds__(256)
void exact_score_kernel(const float* __restrict__ x,
                        const float* __restrict__ W,
                        const float* __restrict__ bias,
                        int D, int O)
{
    const int row = blockIdx.y;
    const int slot = blockIdx.x;
    if (slot >= g_ccnt[row]) return;
    const int col = g_cand[(size_t)row * CAP + slot];

    const float* xr = x + (size_t)row * D;
    const float* wr = W + (size_t)col * D;

    double acc = 0.0;
    for (int i = threadIdx.x; i < D; i += 256)
        acc += (double)xr[i] * (double)wr[i];

    __shared__ double red[256];
    red[threadIdx.x] = acc;
    __syncthreads();
    for (int off = 128; off > 0; off >>= 1) {
        if (threadIdx.x < off) red[threadIdx.x] += red[threadIdx.x + off];
        __syncthreads();
    }
    if (threadIdx.x == 0)
        g_exact[(size_t)row * CAP + slot] = red[0] + (double)bias[col];
}

// ---------------------------------------------------------------------------
// Finalize: rank candidates by exact score (desc, index asc on ties) and
// set mask for the top 'need' of them.
// ---------------------------------------------------------------------------
__global__ void finalize_kernel(unsigned char* __restrict__ mask, int O)
{
    const int row = blockIdx.x;
    if (threadIdx.x != 0) return;
    int C = g_ccnt[row];
    int need = g_need[row];
    if (C <= 0 || need <= 0) return;
    if (C > CAP) C = CAP;
    if (need > C) need = C;

    double sc[CAP];
    int    id[CAP];
    for (int j = 0; j < C; j++) {
        sc[j] = g_exact[(size_t)row * CAP + j];
        id[j] = g_cand [(size_t)row * CAP + j];
    }
    // insertion sort: score desc, index asc for equal scores
    for (int a = 1; a < C; a++) {
        double v = sc[a]; int vi = id[a];
        int b = a - 1;
        while (b >= 0 && (sc[b] < v || (sc[b] == v && id[b] > vi))) {
            sc[b + 1] = sc[b]; id[b + 1] = id[b]; b--;
        }
        sc[b + 1] = v; id[b + 1] = vi;
    }
    unsigned char* mrow = mask + (size_t)row * O;
    for (int j = 0; j < need; j++) mrow[id[j]] = 1;
}

// ---------------------------------------------------------------------------
// kernel_launch
// ---------------------------------------------------------------------------
extern "C" void kernel_launch(void* const* d_in, const int* in_sizes, int n_in,
                              void* d_out, int out_size)
{
    const float* x  = (const float*)d_in[0];
    const float* Wr = (const float*)d_in[1];
    const float* br = (const float*)d_in[2];
    const float* Wo = (const float*)d_in[3];
    const float* bo = (const float*)d_in[4];
    float* out = (float*)d_out;

    const int O = in_sizes[2];
    const int D = in_sizes[1] / O;
    const int N = in_sizes[0] / D;
    int k = (int)(((long long)O * 25LL) / 100LL);
    if (k < 1) k = 1;

    float* R = nullptr;
    unsigned char* M = nullptr;
    cudaGetSymbolAddress((void**)&R, g_router);
    cudaGetSymbolAddress((void**)&M, g_mask);

    dim3 block(256);
    dim3 grid((O + BN - 1) / BN, (N + BM - 1) / BM);

    // 1) Router scores (fp32)
    gemm_nt_kernel<<<grid, block>>>(x, Wr, br, R, nullptr, N, O, D, 0);

    // 2) Top-k: radix select + boundary band
    topk_select_kernel<<<N, TPK_THREADS>>>(R, M, O, k);

    // 3) Exact fp64 re-rank of boundary candidates
    {
        dim3 eg(CAP, N);
        exact_score_kernel<<<eg, 256>>>(x, Wr, br, D, O);
        finalize_kernel<<<N, 32>>>(M, O);
    }

    // 4) Original projection, masked
    gemm_nt_kernel<<<grid, block>>>(x, Wo, bo, out, M, N, O, D, 1);
}

// round 6
// speedup vs baseline: 2.2651x; 2.2651x over previous
#include <cuda_runtime.h>
#include <cuda_bf16.h>
#include <cstdint>

#define N_MAX 8192
#define O_MAX 4096
#define D_MAX 4096
#define CAP   32
#define BAND_EPS 2e-4f

__device__ float         g_router[(size_t)N_MAX * O_MAX];
__device__ unsigned char g_mask  [(size_t)N_MAX * O_MAX];
__device__ int           g_cand  [(size_t)N_MAX * CAP];
__device__ double        g_exact [(size_t)N_MAX * CAP];
__device__ int           g_need  [N_MAX];
__device__ int           g_ccnt  [N_MAX];
__device__ __nv_bfloat16 g_x2 [(size_t)2 * N_MAX * D_MAX];
__device__ __nv_bfloat16 g_wr2[(size_t)2 * O_MAX * D_MAX];
__device__ __nv_bfloat16 g_wo2[(size_t)2 * O_MAX * D_MAX];

// ---- sm_80-era primitives (valid on PTX target sm_100) ----
__device__ __forceinline__ uint32_t smem_u32(const void* p) {
    return (uint32_t)__cvta_generic_to_shared(p);
}
__device__ __forceinline__ void cp_async16(uint32_t s, const void* g) {
    asm volatile("cp.async.cg.shared.global [%0], [%1], 16;"
                 :: "r"(s), "l"(__cvta_generic_to_global(g)) : "memory");
}
#define CP_COMMIT() asm volatile("cp.async.commit_group;" ::: "memory")
template <int K> __device__ __forceinline__ void cp_wait() {
    asm volatile("cp.async.wait_group %0;" :: "n"(K) : "memory");
}
__device__ __forceinline__ void ldsm4(uint32_t* r, uint32_t addr) {
    asm volatile("ldmatrix.sync.aligned.m8n8.x4.shared.b16 {%0,%1,%2,%3}, [%4];"
                 : "=r"(r[0]), "=r"(r[1]), "=r"(r[2]), "=r"(r[3]) : "r"(addr));
}
__device__ __forceinline__ void mma16816(float* c, const uint32_t* a, uint32_t b0, uint32_t b1) {
    asm volatile("mma.sync.aligned.m16n8k16.row.col.f32.bf16.bf16.f32 "
                 "{%0,%1,%2,%3}, {%4,%5,%6,%7}, {%8,%9}, {%0,%1,%2,%3};"
                 : "+f"(c[0]), "+f"(c[1]), "+f"(c[2]), "+f"(c[3])
                 : "r"(a[0]), "r"(a[1]), "r"(a[2]), "r"(a[3]), "r"(b0), "r"(b1));
}

// ---- bf16 hi/lo split ----
__global__ __launch_bounds__(256)
void split2_kernel(const float* __restrict__ src, __nv_bfloat16* __restrict__ dst, size_t n)
{
    size_t i4 = (size_t)blockIdx.x * blockDim.x + threadIdx.x;
    if (i4 >= (n >> 2)) return;
    float4 a = reinterpret_cast<const float4*>(src)[i4];
    __nv_bfloat16 h0 = __float2bfloat16(a.x), h1 = __float2bfloat16(a.y);
    __nv_bfloat16 h2 = __float2bfloat16(a.z), h3 = __float2bfloat16(a.w);
    __nv_bfloat162* H = reinterpret_cast<__nv_bfloat162*>(dst);
    __nv_bfloat162* L = reinterpret_cast<__nv_bfloat162*>(dst + n);
    H[i4 * 2 + 0] = __nv_bfloat162{h0, h1};
    H[i4 * 2 + 1] = __nv_bfloat162{h2, h3};
    L[i4 * 2 + 0] = __nv_bfloat162{__float2bfloat16(a.x - __bfloat162float(h0)),
                                   __float2bfloat16(a.y - __bfloat162float(h1))};
    L[i4 * 2 + 1] = __nv_bfloat162{__float2bfloat16(a.z - __bfloat162float(h2)),
                                   __float2bfloat16(a.w - __bfloat162float(h3))};
}

// ---- HMMA GEMM: 3-term bf16 split, CTA 128x128, warp 32x64, K-chunk 32 ----
#define NSTAGE 4
#define STG 40960u
#define AOFF1 10240u
#define BOFF0 20480u
#define BOFF1 30720u
#define ROWB 80u
#define GEMM_SMEM (NSTAGE * STG)
#define GROUPM 16

__global__ __launch_bounds__(256, 1)
void hmma_gemm_kernel(const __nv_bfloat16* __restrict__ A2, const __nv_bfloat16* __restrict__ B2,
                      const float* __restrict__ bias, float* __restrict__ Cout,
                      const unsigned char* __restrict__ mask,
                      int NR, int OC, int D, int mode, int ntn)
{
    extern __shared__ char smem[];
    const uint32_t sb = smem_u32(smem);
    const int tid = threadIdx.x, wid = tid >> 5, lane = tid & 31;
    const int wm = wid & 3, wn = wid >> 2;

    // CTA swizzle: GROUPM m-tiles share L2-resident x band across all n-tiles
    const int per = GROUPM * ntn;
    const int grp = blockIdx.x / per, rem = blockIdx.x % per;
    const int row0 = (grp * GROUPM + rem % GROUPM) * 128;
    const int col0 = (rem / GROUPM) * 128;

    const int KCH = D >> 5;
    const size_t plA = (size_t)NR * D, plB = (size_t)OC * D;

    auto load_stage = [&](int slot, int kt) {
        const uint32_t st = sb + (uint32_t)slot * STG;
        const int k0 = kt << 5;
#pragma unroll
        for (int h = 0; h < 2; h++) {
            const int c = tid + (h << 8);
            const int row = c >> 2, jc = c & 3;
            const uint32_t so = (uint32_t)row * ROWB + (uint32_t)jc * 16u;
            const __nv_bfloat16* ga = A2 + (size_t)(row0 + row) * D + k0 + jc * 8;
            const __nv_bfloat16* gb = B2 + (size_t)(col0 + row) * D + k0 + jc * 8;
            cp_async16(st + so,         ga);
            cp_async16(st + AOFF1 + so, ga + plA);
            cp_async16(st + BOFF0 + so, gb);
            cp_async16(st + BOFF1 + so, gb + plB);
        }
    };

    float acc[2][8][4];
#pragma unroll
    for (int i = 0; i < 2; i++)
#pragma unroll
        for (int j = 0; j < 8; j++)
#pragma unroll
            for (int q = 0; q < 4; q++) acc[i][j][q] = 0.0f;

    for (int s = 0; s < NSTAGE - 1; s++) { load_stage(s, s); CP_COMMIT(); }

    // ldmatrix lane addressing: x4 matrices (r0-7,k0),(r8-15,k0),(r0-7,k8),(r8-15,k8)
    const uint32_t rIn16 = (uint32_t)(((lane >> 3) & 1) * 8 + (lane & 7));
    const uint32_t cOff  = (uint32_t)((lane >> 4) * 8);

    for (int c = 0; c < KCH; c++) {
        const int s = c & (NSTAGE - 1);
        cp_wait<NSTAGE - 2>();
        __syncthreads();
        if (c + NSTAGE - 1 < KCH) load_stage((c + NSTAGE - 1) & (NSTAGE - 1), c + NSTAGE - 1);
        CP_COMMIT();
        const uint32_t st = sb + (uint32_t)s * STG;
#pragma unroll
        for (int kk = 0; kk < 2; kk++) {
            uint32_t a[2][2][4], b[2][4][4];
            const uint32_t colb = (uint32_t)(kk * 16 + cOff) * 2u;
#pragma unroll
            for (int mt = 0; mt < 2; mt++) {
                const uint32_t r = (uint32_t)(wm * 32 + mt * 16) + rIn16;
                ldsm4(a[0][mt], st + r * ROWB + colb);
                ldsm4(a[1][mt], st + AOFF1 + r * ROWB + colb);
            }
#pragma unroll
            for (int g = 0; g < 4; g++) {
                const uint32_t r = (uint32_t)(wn * 64 + g * 16) + rIn16;
                ldsm4(b[0][g], st + BOFF0 + r * ROWB + colb);
                ldsm4(b[1][g], st + BOFF1 + r * ROWB + colb);
            }
#pragma unroll
            for (int mt = 0; mt < 2; mt++)
#pragma unroll
                for (int j = 0; j < 8; j++) {
                    const int g = j >> 1, sub = j & 1;
                    mma16816(acc[mt][j], a[0][mt], b[0][g][sub], b[0][g][sub + 2]);
                    mma16816(acc[mt][j], a[0][mt], b[1][g][sub], b[1][g][sub + 2]);
                    mma16816(acc[mt][j], a[1][mt], b[0][g][sub], b[0][g][sub + 2]);
                }
        }
    }

    // epilogue: acc regs -> global, fused bias (+ mask)
    const int g = lane >> 2, t = lane & 3;
#pragma unroll
    for (int mt = 0; mt < 2; mt++)
#pragma unroll
        for (int j = 0; j < 8; j++) {
            const int gcol = col0 + wn * 64 + j * 8 + t * 2;
            const float2 bb = *reinterpret_cast<const float2*>(&bias[gcol]);
            const int rlo = row0 + wm * 32 + mt * 16 + g;
            float v0 = acc[mt][j][0] + bb.x, v1 = acc[mt][j][1] + bb.y;
            float v2 = acc[mt][j][2] + bb.x, v3 = acc[mt][j][3] + bb.y;
            const size_t i0 = (size_t)rlo * OC + gcol;
            const size_t i1 = i0 + (size_t)8 * OC;
            if (mode == 1) {
                v0 = mask[i0] ? v0 : 0.0f;     v1 = mask[i0 + 1] ? v1 : 0.0f;
                v2 = mask[i1] ? v2 : 0.0f;     v3 = mask[i1 + 1] ? v3 : 0.0f;
            }
            *reinterpret_cast<float2*>(&Cout[i0]) = make_float2(v0, v1);
            *reinterpret_cast<float2*>(&Cout[i1]) = make_float2(v2, v3);
        }
}

// ---- exact top-k: radix select + band + fp64 re-rank (validated R3) ----
#define TPK 256
__device__ __forceinline__ unsigned int f2key(float f) {
    unsigned int b = __float_as_uint(f);
    return (b & 0x80000000u) ? ~b : (b | 0x80000000u);
}
__device__ __forceinline__ float key2f(unsigned int u) {
    unsigned int b = (u & 0x80000000u) ? (u ^ 0x80000000u) : ~u;
    return __uint_as_float(b);
}

__global__ __launch_bounds__(TPK)
void topk_select_kernel(const float* __restrict__ R, unsigned char* __restrict__ mask, int O, int k)
{
    __shared__ float s[O_MAX];
    __shared__ unsigned int hist[256];
    __shared__ unsigned int s_pre, s_pm, s_rem;
    __shared__ int s_G, s_C, s_fb;
    const int row = blockIdx.x;
    const float* r = R + (size_t)row * O;
    unsigned char* mrow = mask + (size_t)row * O;

    for (int i = threadIdx.x; i < O; i += TPK) s[i] = r[i];
    if (threadIdx.x == 0) { s_pre = 0; s_pm = 0; s_rem = k; s_G = 0; s_C = 0; s_fb = 0; }
    __syncthreads();
    for (int pass = 0; pass < 4; pass++) {
        const int sh = 24 - 8 * pass;
        hist[threadIdx.x] = 0;
        __syncthreads();
        const unsigned int pm = s_pm, pv = s_pre;
        for (int i = threadIdx.x; i < O; i += TPK) {
            unsigned int u = f2key(s[i]);
            if ((u & pm) == pv) atomicAdd(&hist[(u >> sh) & 0xFFu], 1u);
        }
        __syncthreads();
        if (threadIdx.x == 0) {
            unsigned int cum = 0; int b = 255;
            for (; b >= 0; b--) {
                unsigned int cc = hist[b];
                if (cum + cc >= s_rem) { s_rem -= cum; break; }
                cum += cc;
            }
            if (b < 0) b = 0;
            s_pre |= ((unsigned int)b) << sh;
            s_pm |= 0xFFu << sh;
        }
        __syncthreads();
    }
    const unsigned int kT = s_pre;
    const float T = key2f(kT), hi = T + BAND_EPS, lo = T - BAND_EPS;
    for (int i = threadIdx.x; i < O; i += TPK) {
        float v = s[i];
        if (v > hi) { mrow[i] = 1; atomicAdd(&s_G, 1); }
        else {
            mrow[i] = 0;
            if (v >= lo) {
                int p = atomicAdd(&s_C, 1);
                if (p < CAP) g_cand[(size_t)row * CAP + p] = i;
            }
        }
    }
    __syncthreads();
    if (threadIdx.x == 0) {
        if (s_C <= CAP) {
            g_ccnt[row] = s_C;
            int need = k - s_G;
            need = need < 0 ? 0 : (need > s_C ? s_C : need);
            g_need[row] = need;
        } else { s_fb = 1; g_ccnt[row] = 0; g_need[row] = 0; }
    }
    __syncthreads();
    if (s_fb) {
        for (int i = threadIdx.x; i < O; i += TPK) mrow[i] = (f2key(s[i]) > kT) ? 1 : 0;
        __syncthreads();
        if (threadIdx.x == 0) {
            int q = (int)s_rem;
            for (int i = 0; i < O && q > 0; i++)
                if (f2key(s[i]) == kT) { mrow[i] = 1; q--; }
        }
    }
}

__global__ __launch_bounds__(256)
void exact_score_kernel(const float* __restrict__ x, const float* __restrict__ W,
                        const float* __restrict__ bias, int D, int O)
{
    const int row = blockIdx.y, slot = blockIdx.x;
    if (slot >= g_ccnt[row]) return;
    const int col = g_cand[(size_t)row * CAP + slot];
    const float* xr = x + (size_t)row * D;
    const float* wr = W + (size_t)col * D;
    double a = 0.0;
    for (int i = threadIdx.x; i < D; i += 256) a += (double)xr[i] * (double)wr[i];
    __shared__ double red[256];
    red[threadIdx.x] = a;
    __syncthreads();
    for (int o = 128; o > 0; o >>= 1) {
        if (threadIdx.x < o) red[threadIdx.x] += red[threadIdx.x + o];
        __syncthreads();
    }
    if (threadIdx.x == 0) g_exact[(size_t)row * CAP + slot] = red[0] + (double)bias[col];
}

__global__ void finalize_kernel(unsigned char* __restrict__ mask, int O)
{
    const int row = blockIdx.x;
    if (threadIdx.x != 0) return;
    int C = g_ccnt[row], need = g_need[row];
    if (C <= 0 || need <= 0) return;
    if (C > CAP) C = CAP;
    if (need > C) need = C;
    double sc[CAP]; int id[CAP];
    for (int j = 0; j < C; j++) { sc[j] = g_exact[(size_t)row * CAP + j]; id[j] = g_cand[(size_t)row * CAP + j]; }
    for (int a = 1; a < C; a++) {
        double v = sc[a]; int vi = id[a]; int b = a - 1;
        while (b >= 0 && (sc[b] < v || (sc[b] == v && id[b] > vi))) { sc[b+1] = sc[b]; id[b+1] = id[b]; b--; }
        sc[b+1] = v; id[b+1] = vi;
    }
    unsigned char* mrow = mask + (size_t)row * O;
    for (int j = 0; j < need; j++) mrow[id[j]] = 1;
}

extern "C" void kernel_launch(void* const* d_in, const int* in_sizes, int n_in,
                              void* d_out, int out_size)
{
    const float* x  = (const float*)d_in[0];
    const float* Wr = (const float*)d_in[1];
    const float* br = (const float*)d_in[2];
    const float* Wo = (const float*)d_in[3];
    const float* bo = (const float*)d_in[4];
    float* out = (float*)d_out;
    const int O = in_sizes[2];
    const int D = in_sizes[1] / O;
    const int N = in_sizes[0] / D;
    int k = (int)(((long long)O * 25LL) / 100LL);
    if (k < 1) k = 1;

    float* R; unsigned char* M;
    __nv_bfloat16 *X2, *WR2, *WO2;
    cudaGetSymbolAddress((void**)&R,  g_router);
    cudaGetSymbolAddress((void**)&M,  g_mask);
    cudaGetSymbolAddress((void**)&X2, g_x2);
    cudaGetSymbolAddress((void**)&WR2, g_wr2);
    cudaGetSymbolAddress((void**)&WO2, g_wo2);

    const size_t nx = (size_t)N * D, nw = (size_t)O * D;
    split2_kernel<<<(unsigned)((nx / 4 + 255) / 256), 256>>>(x,  X2,  nx);
    split2_kernel<<<(unsigned)((nw / 4 + 255) / 256), 256>>>(Wr, WR2, nw);
    split2_kernel<<<(unsigned)((nw / 4 + 255) / 256), 256>>>(Wo, WO2, nw);

    cudaFuncSetAttribute(hmma_gemm_kernel, cudaFuncAttributeMaxDynamicSharedMemorySize, GEMM_SMEM);
    const int ntm = N / 128, ntn = O / 128;
    hmma_gemm_kernel<<<ntm * ntn, 256, GEMM_SMEM>>>(X2, WR2, br, R, nullptr, N, O, D, 0, ntn);

    topk_select_kernel<<<N, TPK>>>(R, M, O, k);
    dim3 eg(CAP, N);
    exact_score_kernel<<<eg, 256>>>(x, Wr, br, D, O);
    finalize_kernel<<<N, 32>>>(M, O);

    hmma_gemm_kernel<<<ntm * ntn, 256, GEMM_SMEM>>>(X2, WO2, bo, out, M, N, O, D, 1, ntn);
}

// round 7
// speedup vs baseline: 2.3517x; 1.0383x over previous
#include <cuda_runtime.h>
#include <cuda_bf16.h>
#include <cstdint>

#define N_MAX 8192
#define O_MAX 4096
#define D_MAX 4096
#define CAP   32
#define BAND_EPS 2e-4f

__device__ float         g_router[(size_t)N_MAX * O_MAX];
__device__ unsigned char g_mask  [(size_t)N_MAX * O_MAX];
__device__ int           g_cand  [(size_t)N_MAX * CAP];
__device__ double        g_exact [(size_t)N_MAX * CAP];
__device__ int           g_need  [N_MAX];
__device__ int           g_ccnt  [N_MAX];
__device__ __nv_bfloat16 g_x2 [(size_t)2 * N_MAX * D_MAX];
__device__ __nv_bfloat16 g_wr2[(size_t)2 * O_MAX * D_MAX];
__device__ __nv_bfloat16 g_wo2[(size_t)2 * O_MAX * D_MAX];

__device__ __forceinline__ uint32_t smem_u32(const void* p) {
    return (uint32_t)__cvta_generic_to_shared(p);
}
__device__ __forceinline__ void cp_async16(uint32_t s, const void* g) {
    asm volatile("cp.async.cg.shared.global [%0], [%1], 16;"
                 :: "r"(s), "l"(__cvta_generic_to_global(g)) : "memory");
}
#define CP_COMMIT() asm volatile("cp.async.commit_group;" ::: "memory")
template <int K> __device__ __forceinline__ void cp_wait() {
    asm volatile("cp.async.wait_group %0;" :: "n"(K) : "memory");
}
__device__ __forceinline__ void ldsm4(uint32_t* r, uint32_t addr) {
    asm volatile("ldmatrix.sync.aligned.m8n8.x4.shared.b16 {%0,%1,%2,%3}, [%4];"
                 : "=r"(r[0]), "=r"(r[1]), "=r"(r[2]), "=r"(r[3]) : "r"(addr));
}
__device__ __forceinline__ void mma16816(float* c, const uint32_t* a, uint32_t b0, uint32_t b1) {
    asm volatile("mma.sync.aligned.m16n8k16.row.col.f32.bf16.bf16.f32 "
                 "{%0,%1,%2,%3}, {%4,%5,%6,%7}, {%8,%9}, {%0,%1,%2,%3};"
                 : "+f"(c[0]), "+f"(c[1]), "+f"(c[2]), "+f"(c[3])
                 : "r"(a[0]), "r"(a[1]), "r"(a[2]), "r"(a[3]), "r"(b0), "r"(b1));
}

__global__ __launch_bounds__(256)
void split2_kernel(const float* __restrict__ src, __nv_bfloat16* __restrict__ dst, size_t n)
{
    size_t i4 = (size_t)blockIdx.x * blockDim.x + threadIdx.x;
    if (i4 >= (n >> 2)) return;
    float4 a = reinterpret_cast<const float4*>(src)[i4];
    __nv_bfloat16 h0 = __float2bfloat16(a.x), h1 = __float2bfloat16(a.y);
    __nv_bfloat16 h2 = __float2bfloat16(a.z), h3 = __float2bfloat16(a.w);
    __nv_bfloat162* H = reinterpret_cast<__nv_bfloat162*>(dst);
    __nv_bfloat162* L = reinterpret_cast<__nv_bfloat162*>(dst + n);
    H[i4 * 2 + 0] = __nv_bfloat162{h0, h1};
    H[i4 * 2 + 1] = __nv_bfloat162{h2, h3};
    L[i4 * 2 + 0] = __nv_bfloat162{__float2bfloat16(a.x - __bfloat162float(h0)),
                                   __float2bfloat16(a.y - __bfloat162float(h1))};
    L[i4 * 2 + 1] = __nv_bfloat162{__float2bfloat16(a.z - __bfloat162float(h2)),
                                   __float2bfloat16(a.w - __bfloat162float(h3))};
}

// ---- HMMA GEMM: 3-term bf16 split, CTA 128x128, 16 warps, warp 32x32 ----
#define NSTAGE 4
#define STG 40960u
#define AOFF1 10240u
#define BOFF0 20480u
#define BOFF1 30720u
#define ROWB 80u
#define GEMM_SMEM (NSTAGE * STG)
#define GROUPM 16

__global__ __launch_bounds__(512, 1)
void hmma_gemm_kernel(const __nv_bfloat16* __restrict__ A2, const __nv_bfloat16* __restrict__ B2,
                      const float* __restrict__ bias, float* __restrict__ Cout,
                      const unsigned char* __restrict__ mask,
                      int NR, int OC, int D, int mode, int ntn)
{
    extern __shared__ char smem[];
    const uint32_t sb = smem_u32(smem);
    const int tid = threadIdx.x, wid = tid >> 5, lane = tid & 31;
    const int wm = wid & 3, wn = wid >> 2;      // 4x4 warp grid, warp tile 32x32

    const int per = GROUPM * ntn;
    const int grp = blockIdx.x / per, rem = blockIdx.x % per;
    const int row0 = (grp * GROUPM + rem % GROUPM) * 128;
    const int col0 = (rem / GROUPM) * 128;

    const int KCH = D >> 5;
    const size_t plA = (size_t)NR * D, plB = (size_t)OC * D;

    // 512 threads: one cp.async16 per plane per thread (4 total / stage)
    const int lrow = tid >> 2, ljc = tid & 3;
    const uint32_t lso = (uint32_t)lrow * ROWB + (uint32_t)ljc * 16u;
    auto load_stage = [&](int slot, int kt) {
        const uint32_t st = sb + (uint32_t)slot * STG;
        const int k0 = kt << 5;
        const __nv_bfloat16* ga = A2 + (size_t)(row0 + lrow) * D + k0 + ljc * 8;
        const __nv_bfloat16* gb = B2 + (size_t)(col0 + lrow) * D + k0 + ljc * 8;
        cp_async16(st + lso,         ga);
        cp_async16(st + AOFF1 + lso, ga + plA);
        cp_async16(st + BOFF0 + lso, gb);
        cp_async16(st + BOFF1 + lso, gb + plB);
    };

    float acc[2][4][4];
#pragma unroll
    for (int i = 0; i < 2; i++)
#pragma unroll
        for (int j = 0; j < 4; j++)
#pragma unroll
            for (int q = 0; q < 4; q++) acc[i][j][q] = 0.0f;

    for (int s = 0; s < NSTAGE - 1; s++) { load_stage(s, s); CP_COMMIT(); }

    const uint32_t rIn16 = (uint32_t)(((lane >> 3) & 1) * 8 + (lane & 7));
    const uint32_t cOff  = (uint32_t)((lane >> 4) * 8);

    for (int c = 0; c < KCH; c++) {
        const int s = c & (NSTAGE - 1);
        cp_wait<NSTAGE - 2>();
        __syncthreads();
        if (c + NSTAGE - 1 < KCH) load_stage((c + NSTAGE - 1) & (NSTAGE - 1), c + NSTAGE - 1);
        CP_COMMIT();
        const uint32_t st = sb + (uint32_t)s * STG;
#pragma unroll
        for (int kk = 0; kk < 2; kk++) {
            uint32_t a[2][2][4], b[2][2][4];
            const uint32_t colb = (uint32_t)(kk * 16 + cOff) * 2u;
#pragma unroll
            for (int mt = 0; mt < 2; mt++) {
                const uint32_t r = (uint32_t)(wm * 32 + mt * 16) + rIn16;
                ldsm4(a[0][mt], st + r * ROWB + colb);
                ldsm4(a[1][mt], st + AOFF1 + r * ROWB + colb);
            }
#pragma unroll
            for (int g = 0; g < 2; g++) {
                const uint32_t r = (uint32_t)(wn * 32 + g * 16) + rIn16;
                ldsm4(b[0][g], st + BOFF0 + r * ROWB + colb);
                ldsm4(b[1][g], st + BOFF1 + r * ROWB + colb);
            }
#pragma unroll
            for (int mt = 0; mt < 2; mt++)
#pragma unroll
                for (int j = 0; j < 4; j++) {
                    const int g = j >> 1, sub = j & 1;
                    mma16816(acc[mt][j], a[0][mt], b[0][g][sub], b[0][g][sub + 2]);
                    mma16816(acc[mt][j], a[0][mt], b[1][g][sub], b[1][g][sub + 2]);
                    mma16816(acc[mt][j], a[1][mt], b[0][g][sub], b[0][g][sub + 2]);
                }
        }
    }

    const int g = lane >> 2, t = lane & 3;
#pragma unroll
    for (int mt = 0; mt < 2; mt++)
#pragma unroll
        for (int j = 0; j < 4; j++) {
            const int gcol = col0 + wn * 32 + j * 8 + t * 2;
            const float2 bb = *reinterpret_cast<const float2*>(&bias[gcol]);
            const int rlo = row0 + wm * 32 + mt * 16 + g;
            float v0 = acc[mt][j][0] + bb.x, v1 = acc[mt][j][1] + bb.y;
            float v2 = acc[mt][j][2] + bb.x, v3 = acc[mt][j][3] + bb.y;
            const size_t i0 = (size_t)rlo * OC + gcol;
            const size_t i1 = i0 + (size_t)8 * OC;
            if (mode == 1) {
                v0 = mask[i0] ? v0 : 0.0f;     v1 = mask[i0 + 1] ? v1 : 0.0f;
                v2 = mask[i1] ? v2 : 0.0f;     v3 = mask[i1 + 1] ? v3 : 0.0f;
            }
            *reinterpret_cast<float2*>(&Cout[i0]) = make_float2(v0, v1);
            *reinterpret_cast<float2*>(&Cout[i1]) = make_float2(v2, v3);
        }
}

// ---- exact top-k: radix select + band + fp64 re-rank (validated) ----
#define TPK 256
__device__ __forceinline__ unsigned int f2key(float f) {
    unsigned int b = __float_as_uint(f);
    return (b & 0x80000000u) ? ~b : (b | 0x80000000u);
}
__device__ __forceinline__ float key2f(unsigned int u) {
    unsigned int b = (u & 0x80000000u) ? (u ^ 0x80000000u) : ~u;
    return __uint_as_float(b);
}

__global__ __launch_bounds__(TPK)
void topk_select_kernel(const float* __restrict__ R, unsigned char* __restrict__ mask, int O, int k)
{
    __shared__ float s[O_MAX];
    __shared__ unsigned int hist[256];
    __shared__ unsigned int s_pre, s_pm, s_rem;
    __shared__ int s_G, s_C, s_fb;
    const int row = blockIdx.x;
    const float* r = R + (size_t)row * O;
    unsigned char* mrow = mask + (size_t)row * O;

    for (int i = threadIdx.x; i < O; i += TPK) s[i] = r[i];
    if (threadIdx.x == 0) { s_pre = 0; s_pm = 0; s_rem = k; s_G = 0; s_C = 0; s_fb = 0; }
    __syncthreads();
    for (int pass = 0; pass < 4; pass++) {
        const int sh = 24 - 8 * pass;
        hist[threadIdx.x] = 0;
        __syncthreads();
        const unsigned int pm = s_pm, pv = s_pre;
        for (int i = threadIdx.x; i < O; i += TPK) {
            unsigned int u = f2key(s[i]);
            if ((u & pm) == pv) atomicAdd(&hist[(u >> sh) & 0xFFu], 1u);
        }
        __syncthreads();
        if (threadIdx.x == 0) {
            unsigned int cum = 0; int b = 255;
            for (; b >= 0; b--) {
                unsigned int cc = hist[b];
                if (cum + cc >= s_rem) { s_rem -= cum; break; }
                cum += cc;
            }
            if (b < 0) b = 0;
            s_pre |= ((unsigned int)b) << sh;
            s_pm |= 0xFFu << sh;
        }
        __syncthreads();
    }
    const unsigned int kT = s_pre;
    const float T = key2f(kT), hi = T + BAND_EPS, lo = T - BAND_EPS;
    for (int i = threadIdx.x; i < O; i += TPK) {
        float v = s[i];
        if (v > hi) { mrow[i] = 1; atomicAdd(&s_G, 1); }
        else {
            mrow[i] = 0;
            if (v >= lo) {
                int p = atomicAdd(&s_C, 1);
                if (p < CAP) g_cand[(size_t)row * CAP + p] = i;
            }
        }
    }
    __syncthreads();
    if (threadIdx.x == 0) {
        if (s_C <= CAP) {
            g_ccnt[row] = s_C;
            int need = k - s_G;
            need = need < 0 ? 0 : (need > s_C ? s_C : need);
            g_need[row] = need;
        } else { s_fb = 1; g_ccnt[row] = 0; g_need[row] = 0; }
    }
    __syncthreads();
    if (s_fb) {
        for (int i = threadIdx.x; i < O; i += TPK) mrow[i] = (f2key(s[i]) > kT) ? 1 : 0;
        __syncthreads();
        if (threadIdx.x == 0) {
            int q = (int)s_rem;
            for (int i = 0; i < O && q > 0; i++)
                if (f2key(s[i]) == kT) { mrow[i] = 1; q--; }
        }
    }
}

__global__ __launch_bounds__(256)
void exact_score_kernel(const float* __restrict__ x, const float* __restrict__ W,
                        const float* __restrict__ bias, int D, int O)
{
    const int row = blockIdx.y, slot = blockIdx.x;
    if (slot >= g_ccnt[row]) return;
    const int col = g_cand[(size_t)row * CAP + slot];
    const float* xr = x + (size_t)row * D;
    const float* wr = W + (size_t)col * D;
    double a = 0.0;
    for (int i = threadIdx.x; i < D; i += 256) a += (double)xr[i] * (double)wr[i];
    __shared__ double red[256];
    red[threadIdx.x] = a;
    __syncthreads();
    for (int o = 128; o > 0; o >>= 1) {
        if (threadIdx.x < o) red[threadIdx.x] += red[threadIdx.x + o];
        __syncthreads();
    }
    if (threadIdx.x == 0) g_exact[(size_t)row * CAP + slot] = red[0] + (double)bias[col];
}

__global__ void finalize_kernel(unsigned char* __restrict__ mask, int O)
{
    const int row = blockIdx.x;
    if (threadIdx.x != 0) return;
    int C = g_ccnt[row], need = g_need[row];
    if (C <= 0 || need <= 0) return;
    if (C > CAP) C = CAP;
    if (need > C) need = C;
    double sc[CAP]; int id[CAP];
    for (int j = 0; j < C; j++) { sc[j] = g_exact[(size_t)row * CAP + j]; id[j] = g_cand[(size_t)row * CAP + j]; }
    for (int a = 1; a < C; a++) {
        double v = sc[a]; int vi = id[a]; int b = a - 1;
        while (b >= 0 && (sc[b] < v || (sc[b] == v && id[b] > vi))) { sc[b+1] = sc[b]; id[b+1] = id[b]; b--; }
        sc[b+1] = v; id[b+1] = vi;
    }
    unsigned char* mrow = mask + (size_t)row * O;
    for (int j = 0; j < need; j++) mrow[id[j]] = 1;
}

extern "C" void kernel_launch(void* const* d_in, const int* in_sizes, int n_in,
                              void* d_out, int out_size)
{
    const float* x  = (const float*)d_in[0];
    const float* Wr = (const float*)d_in[1];
    const float* br = (const float*)d_in[2];
    const float* Wo = (const float*)d_in[3];
    const float* bo = (const float*)d_in[4];
    float* out = (float*)d_out;
    const int O = in_sizes[2];
    const int D = in_sizes[1] / O;
    const int N = in_sizes[0] / D;
    int k = (int)(((long long)O * 25LL) / 100LL);
    if (k < 1) k = 1;

    float* R; unsigned char* M;
    __nv_bfloat16 *X2, *WR2, *WO2;
    cudaGetSymbolAddress((void**)&R,  g_router);
    cudaGetSymbolAddress((void**)&M,  g_mask);
    cudaGetSymbolAddress((void**)&X2, g_x2);
    cudaGetSymbolAddress((void**)&WR2, g_wr2);
    cudaGetSymbolAddress((void**)&WO2, g_wo2);

    const size_t nx = (size_t)N * D, nw = (size_t)O * D;
    split2_kernel<<<(unsigned)((nx / 4 + 255) / 256), 256>>>(x,  X2,  nx);
    split2_kernel<<<(unsigned)((nw / 4 + 255) / 256), 256>>>(Wr, WR2, nw);
    split2_kernel<<<(unsigned)((nw / 4 + 255) / 256), 256>>>(Wo, WO2, nw);

    cudaFuncSetAttribute(hmma_gemm_kernel, cudaFuncAttributeMaxDynamicSharedMemorySize, GEMM_SMEM);
    const int ntm = N / 128, ntn = O / 128;
    hmma_gemm_kernel<<<ntm * ntn, 512, GEMM_SMEM>>>(X2, WR2, br, R, nullptr, N, O, D, 0, ntn);

    topk_select_kernel<<<N, TPK>>>(R, M, O, k);
    dim3 eg(CAP, N);
    exact_score_kernel<<<eg, 256>>>(x, Wr, br, D, O);
    finalize_kernel<<<N, 32>>>(M, O);

    hmma_gemm_kernel<<<ntm * ntn, 512, GEMM_SMEM>>>(X2, WO2, bo, out, M, N, O, D, 1, ntn);
}

// round 8
// speedup vs baseline: 2.4973x; 1.0619x over previous
#include <cuda_runtime.h>
#include <cuda_bf16.h>
#include <cstdint>

#define N_MAX 8192
#define O_MAX 4096
#define D_MAX 4096
#define CAP   32
#define BAND_EPS 2e-4f

__device__ float         g_router[(size_t)N_MAX * O_MAX];
__device__ unsigned char g_mask  [(size_t)N_MAX * O_MAX];
__device__ int           g_cand  [(size_t)N_MAX * CAP];
__device__ double        g_exact [(size_t)N_MAX * CAP];
__device__ int           g_need  [N_MAX];
__device__ int           g_ccnt  [N_MAX];
__device__ __nv_bfloat16 g_x2 [(size_t)2 * N_MAX * D_MAX];
__device__ __nv_bfloat16 g_wr2[(size_t)2 * O_MAX * D_MAX];
__device__ __nv_bfloat16 g_wo2[(size_t)2 * O_MAX * D_MAX];

__device__ __forceinline__ uint32_t smem_u32(const void* p) {
    return (uint32_t)__cvta_generic_to_shared(p);
}
__device__ __forceinline__ void cp_async16(uint32_t s, const void* g) {
    asm volatile("cp.async.cg.shared.global [%0], [%1], 16;"
                 :: "r"(s), "l"(__cvta_generic_to_global(g)) : "memory");
}
#define CP_COMMIT() asm volatile("cp.async.commit_group;" ::: "memory")
template <int K> __device__ __forceinline__ void cp_wait() {
    asm volatile("cp.async.wait_group %0;" :: "n"(K) : "memory");
}
__device__ __forceinline__ void ldsm4(uint32_t* r, uint32_t addr) {
    asm volatile("ldmatrix.sync.aligned.m8n8.x4.shared.b16 {%0,%1,%2,%3}, [%4];"
                 : "=r"(r[0]), "=r"(r[1]), "=r"(r[2]), "=r"(r[3]) : "r"(addr));
}
__device__ __forceinline__ void mma16816(float* c, const uint32_t* a, uint32_t b0, uint32_t b1) {
    asm volatile("mma.sync.aligned.m16n8k16.row.col.f32.bf16.bf16.f32 "
                 "{%0,%1,%2,%3}, {%4,%5,%6,%7}, {%8,%9}, {%0,%1,%2,%3};"
                 : "+f"(c[0]), "+f"(c[1]), "+f"(c[2]), "+f"(c[3])
                 : "r"(a[0]), "r"(a[1]), "r"(a[2]), "r"(a[3]), "r"(b0), "r"(b1));
}

__global__ __launch_bounds__(256)
void split2_kernel(const float* __restrict__ src, __nv_bfloat16* __restrict__ dst, size_t n)
{
    size_t i4 = (size_t)blockIdx.x * blockDim.x + threadIdx.x;
    if (i4 >= (n >> 2)) return;
    float4 a = reinterpret_cast<const float4*>(src)[i4];
    __nv_bfloat16 h0 = __float2bfloat16(a.x), h1 = __float2bfloat16(a.y);
    __nv_bfloat16 h2 = __float2bfloat16(a.z), h3 = __float2bfloat16(a.w);
    __nv_bfloat162* H = reinterpret_cast<__nv_bfloat162*>(dst);
    __nv_bfloat162* L = reinterpret_cast<__nv_bfloat162*>(dst + n);
    H[i4 * 2 + 0] = __nv_bfloat162{h0, h1};
    H[i4 * 2 + 1] = __nv_bfloat162{h2, h3};
    L[i4 * 2 + 0] = __nv_bfloat162{__float2bfloat16(a.x - __bfloat162float(h0)),
                                   __float2bfloat16(a.y - __bfloat162float(h1))};
    L[i4 * 2 + 1] = __nv_bfloat162{__float2bfloat16(a.z - __bfloat162float(h2)),
                                   __float2bfloat16(a.w - __bfloat162float(h3))};
}

// ---- HMMA GEMM: 3-term bf16 split, CTA 128x256, 8 warps, warp 64x64 ----
#define NSTAGE 3
#define ROWB 80u
#define APLANE 10240u            /* 128 rows * 80B */
#define BPLANE 20480u            /* 256 rows * 80B */
#define AOFF1 10240u
#define BOFF0 20480u
#define BOFF1 40960u
#define STG   61440u
#define GEMM_SMEM (NSTAGE * STG)
#define GROUPM 16

__global__ __launch_bounds__(256, 1)
void hmma_gemm_kernel(const __nv_bfloat16* __restrict__ A2, const __nv_bfloat16* __restrict__ B2,
                      const float* __restrict__ bias, float* __restrict__ Cout,
                      const unsigned char* __restrict__ mask,
                      int NR, int OC, int D, int mode, int ntn)
{
    extern __shared__ char smem[];
    const uint32_t sb = smem_u32(smem);
    const int tid = threadIdx.x, wid = tid >> 5, lane = tid & 31;
    const int wm = wid & 1, wn = wid >> 1;      // 2x4 warp grid, warp tile 64x64

    const int per = GROUPM * ntn;
    const int grp = blockIdx.x / per, rem = blockIdx.x % per;
    const int row0 = (grp * GROUPM + rem % GROUPM) * 128;
    const int col0 = (rem / GROUPM) * 256;

    const int KCH = D >> 5;
    const size_t plA = (size_t)NR * D, plB = (size_t)OC * D;

    const int lrow = tid >> 2, ljc = tid & 3;   // lrow 0..63, ljc 0..3
    auto load_stage = [&](int slot, int kt) {
        const uint32_t st = sb + (uint32_t)slot * STG;
        const int k0 = kt << 5;
#pragma unroll
        for (int i = 0; i < 2; i++) {           // A: 128 rows
            const int row = lrow + 64 * i;
            const uint32_t so = (uint32_t)row * ROWB + (uint32_t)ljc * 16u;
            const __nv_bfloat16* ga = A2 + (size_t)(row0 + row) * D + k0 + ljc * 8;
            cp_async16(st + so,         ga);
            cp_async16(st + AOFF1 + so, ga + plA);
        }
#pragma unroll
        for (int i = 0; i < 4; i++) {           // B: 256 rows
            const int row = lrow + 64 * i;
            const uint32_t so = (uint32_t)row * ROWB + (uint32_t)ljc * 16u;
            const __nv_bfloat16* gb = B2 + (size_t)(col0 + row) * D + k0 + ljc * 8;
            cp_async16(st + BOFF0 + so, gb);
            cp_async16(st + BOFF1 + so, gb + plB);
        }
    };

    float acc[4][8][4];
#pragma unroll
    for (int i = 0; i < 4; i++)
#pragma unroll
        for (int j = 0; j < 8; j++)
#pragma unroll
            for (int q = 0; q < 4; q++) acc[i][j][q] = 0.0f;

    for (int s = 0; s < NSTAGE - 1; s++) { load_stage(s, s); CP_COMMIT(); }

    const uint32_t rIn16 = (uint32_t)(((lane >> 3) & 1) * 8 + (lane & 7));
    const uint32_t cOff  = (uint32_t)((lane >> 4) * 8);

    for (int c = 0; c < KCH; c++) {
        const int s = c % NSTAGE;
        cp_wait<NSTAGE - 2>();
        __syncthreads();
        if (c + NSTAGE - 1 < KCH) load_stage((c + NSTAGE - 1) % NSTAGE, c + NSTAGE - 1);
        CP_COMMIT();
        const uint32_t st = sb + (uint32_t)s * STG;
#pragma unroll
        for (int kk = 0; kk < 2; kk++) {
            uint32_t a[2][4][4], b[2][4][4];
            const uint32_t colb = (uint32_t)(kk * 16 + cOff) * 2u;
#pragma unroll
            for (int mt = 0; mt < 4; mt++) {
                const uint32_t r = (uint32_t)(wm * 64 + mt * 16) + rIn16;
                ldsm4(a[0][mt], st + r * ROWB + colb);
                ldsm4(a[1][mt], st + AOFF1 + r * ROWB + colb);
            }
#pragma unroll
            for (int g = 0; g < 4; g++) {
                const uint32_t r = (uint32_t)(wn * 64 + g * 16) + rIn16;
                ldsm4(b[0][g], st + BOFF0 + r * ROWB + colb);
                ldsm4(b[1][g], st + BOFF1 + r * ROWB + colb);
            }
#pragma unroll
            for (int mt = 0; mt < 4; mt++)
#pragma unroll
                for (int j = 0; j < 8; j++) {
                    const int g = j >> 1, sub = j & 1;
                    mma16816(acc[mt][j], a[0][mt], b[0][g][sub], b[0][g][sub + 2]);
                    mma16816(acc[mt][j], a[0][mt], b[1][g][sub], b[1][g][sub + 2]);
                    mma16816(acc[mt][j], a[1][mt], b[0][g][sub], b[0][g][sub + 2]);
                }
        }
    }

    const int g = lane >> 2, t = lane & 3;
#pragma unroll
    for (int mt = 0; mt < 4; mt++)
#pragma unroll
        for (int j = 0; j < 8; j++) {
            const int gcol = col0 + wn * 64 + j * 8 + t * 2;
            const float2 bb = *reinterpret_cast<const float2*>(&bias[gcol]);
            const int rlo = row0 + wm * 64 + mt * 16 + g;
            float v0 = acc[mt][j][0] + bb.x, v1 = acc[mt][j][1] + bb.y;
            float v2 = acc[mt][j][2] + bb.x, v3 = acc[mt][j][3] + bb.y;
            const size_t i0 = (size_t)rlo * OC + gcol;
            const size_t i1 = i0 + (size_t)8 * OC;
            if (mode == 1) {
                v0 = mask[i0] ? v0 : 0.0f;     v1 = mask[i0 + 1] ? v1 : 0.0f;
                v2 = mask[i1] ? v2 : 0.0f;     v3 = mask[i1 + 1] ? v3 : 0.0f;
            }
            *reinterpret_cast<float2*>(&Cout[i0]) = make_float2(v0, v1);
            *reinterpret_cast<float2*>(&Cout[i1]) = make_float2(v2, v3);
        }
}

// ---- exact top-k: radix select + band + fp64 re-rank (validated) ----
#define TPK 256
__device__ __forceinline__ unsigned int f2key(float f) {
    unsigned int b = __float_as_uint(f);
    return (b & 0x80000000u) ? ~b : (b | 0x80000000u);
}
__device__ __forceinline__ float key2f(unsigned int u) {
    unsigned int b = (u & 0x80000000u) ? (u ^ 0x80000000u) : ~u;
    return __uint_as_float(b);
}

__global__ __launch_bounds__(TPK)
void topk_select_kernel(const float* __restrict__ R, unsigned char* __restrict__ mask, int O, int k)
{
    __shared__ float s[O_MAX];
    __shared__ unsigned int hist[256];
    __shared__ unsigned int s_pre, s_pm, s_rem;
    __shared__ int s_G, s_C, s_fb;
    const int row = blockIdx.x;
    const float* r = R + (size_t)row * O;
    unsigned char* mrow = mask + (size_t)row * O;

    for (int i = threadIdx.x; i < O; i += TPK) s[i] = r[i];
    if (threadIdx.x == 0) { s_pre = 0; s_pm = 0; s_rem = k; s_G = 0; s_C = 0; s_fb = 0; }
    __syncthreads();
    for (int pass = 0; pass < 4; pass++) {
        const int sh = 24 - 8 * pass;
        hist[threadIdx.x] = 0;
        __syncthreads();
        const unsigned int pm = s_pm, pv = s_pre;
        for (int i = threadIdx.x; i < O; i += TPK) {
            unsigned int u = f2key(s[i]);
            if ((u & pm) == pv) atomicAdd(&hist[(u >> sh) & 0xFFu], 1u);
        }
        __syncthreads();
        if (threadIdx.x == 0) {
            unsigned int cum = 0; int b = 255;
            for (; b >= 0; b--) {
                unsigned int cc = hist[b];
                if (cum + cc >= s_rem) { s_rem -= cum; break; }
                cum += cc;
            }
            if (b < 0) b = 0;
            s_pre |= ((unsigned int)b) << sh;
            s_pm |= 0xFFu << sh;
        }
        __syncthreads();
    }
    const unsigned int kT = s_pre;
    const float T = key2f(kT), hi = T + BAND_EPS, lo = T - BAND_EPS;
    for (int i = threadIdx.x; i < O; i += TPK) {
        float v = s[i];
        if (v > hi) { mrow[i] = 1; atomicAdd(&s_G, 1); }
        else {
            mrow[i] = 0;
            if (v >= lo) {
                int p = atomicAdd(&s_C, 1);
                if (p < CAP) g_cand[(size_t)row * CAP + p] = i;
            }
        }
    }
    __syncthreads();
    if (threadIdx.x == 0) {
        if (s_C <= CAP) {
            g_ccnt[row] = s_C;
            int need = k - s_G;
            need = need < 0 ? 0 : (need > s_C ? s_C : need);
            g_need[row] = need;
        } else { s_fb = 1; g_ccnt[row] = 0; g_need[row] = 0; }
    }
    __syncthreads();
    if (s_fb) {
        for (int i = threadIdx.x; i < O; i += TPK) mrow[i] = (f2key(s[i]) > kT) ? 1 : 0;
        __syncthreads();
        if (threadIdx.x == 0) {
            int q = (int)s_rem;
            for (int i = 0; i < O && q > 0; i++)
                if (f2key(s[i]) == kT) { mrow[i] = 1; q--; }
        }
    }
}

__global__ __launch_bounds__(256)
void exact_score_kernel(const float* __restrict__ x, const float* __restrict__ W,
                        const float* __restrict__ bias, int D, int O)
{
    const int row = blockIdx.y, slot = blockIdx.x;
    if (slot >= g_ccnt[row]) return;
    const int col = g_cand[(size_t)row * CAP + slot];
    const float* xr = x + (size_t)row * D;
    const float* wr = W + (size_t)col * D;
    double a = 0.0;
    for (int i = threadIdx.x; i < D; i += 256) a += (double)xr[i] * (double)wr[i];
    __shared__ double red[256];
    red[threadIdx.x] = a;
    __syncthreads();
    for (int o = 128; o > 0; o >>= 1) {
        if (threadIdx.x < o) red[threadIdx.x] += red[threadIdx.x + o];
        __syncthreads();
    }
    if (threadIdx.x == 0) g_exact[(size_t)row * CAP + slot] = red[0] + (double)bias[col];
}

__global__ void finalize_kernel(unsigned char* __restrict__ mask, int O)
{
    const int row = blockIdx.x;
    if (threadIdx.x != 0) return;
    int C = g_ccnt[row], need = g_need[row];
    if (C <= 0 || need <= 0) return;
    if (C > CAP) C = CAP;
    if (need > C) need = C;
    double sc[CAP]; int id[CAP];
    for (int j = 0; j < C; j++) { sc[j] = g_exact[(size_t)row * CAP + j]; id[j] = g_cand[(size_t)row * CAP + j]; }
    for (int a = 1; a < C; a++) {
        double v = sc[a]; int vi = id[a]; int b = a - 1;
        while (b >= 0 && (sc[b] < v || (sc[b] == v && id[b] > vi))) { sc[b+1] = sc[b]; id[b+1] = id[b]; b--; }
        sc[b+1] = v; id[b+1] = vi;
    }
    unsigned char* mrow = mask + (size_t)row * O;
    for (int j = 0; j < need; j++) mrow[id[j]] = 1;
}

extern "C" void kernel_launch(void* const* d_in, const int* in_sizes, int n_in,
                              void* d_out, int out_size)
{
    const float* x  = (const float*)d_in[0];
    const float* Wr = (const float*)d_in[1];
    const float* br = (const float*)d_in[2];
    const float* Wo = (const float*)d_in[3];
    const float* bo = (const float*)d_in[4];
    float* out = (float*)d_out;
    const int O = in_sizes[2];
    const int D = in_sizes[1] / O;
    const int N = in_sizes[0] / D;
    int k = (int)(((long long)O * 25LL) / 100LL);
    if (k < 1) k = 1;

    float* R; unsigned char* M;
    __nv_bfloat16 *X2, *WR2, *WO2;
    cudaGetSymbolAddress((void**)&R,  g_router);
    cudaGetSymbolAddress((void**)&M,  g_mask);
    cudaGetSymbolAddress((void**)&X2, g_x2);
    cudaGetSymbolAddress((void**)&WR2, g_wr2);
    cudaGetSymbolAddress((void**)&WO2, g_wo2);

    const size_t nx = (size_t)N * D, nw = (size_t)O * D;
    split2_kernel<<<(unsigned)((nx / 4 + 255) / 256), 256>>>(x,  X2,  nx);
    split2_kernel<<<(unsigned)((nw / 4 + 255) / 256), 256>>>(Wr, WR2, nw);
    split2_kernel<<<(unsigned)((nw / 4 + 255) / 256), 256>>>(Wo, WO2, nw);

    cudaFuncSetAttribute(hmma_gemm_kernel, cudaFuncAttributeMaxDynamicSharedMemorySize, GEMM_SMEM);
    const int ntm = N / 128, ntn = O / 256;
    hmma_gemm_kernel<<<ntm * ntn, 256, GEMM_SMEM>>>(X2, WR2, br, R, nullptr, N, O, D, 0, ntn);

    topk_select_kernel<<<N, TPK>>>(R, M, O, k);
    dim3 eg(CAP, N);
    exact_score_kernel<<<eg, 256>>>(x, Wr, br, D, O);
    finalize_kernel<<<N, 32>>>(M, O);

    hmma_gemm_kernel<<<ntm * ntn, 256, GEMM_SMEM>>>(X2, WO2, bo, out, M, N, O, D, 1, ntn);
}